// round 11
// baseline (speedup 1.0000x reference)
#include <cuda_runtime.h>
#include <cstdint>

#define IN_CH 16
#define OUT_CH 32
#define BATCH 8
#define H 32
#define W 32
#define NCP (IN_CH / 2)            // 8 channel pairs
#define NTAP 9

typedef unsigned long long ull;

__device__ __forceinline__ ull add2(ull a, ull b) {
    ull r; asm("add.rn.f32x2 %0, %1, %2;" : "=l"(r) : "l"(a), "l"(b)); return r;
}
__device__ __forceinline__ ull fma2(ull a, ull b, ull c) {
    ull r; asm("fma.rn.f32x2 %0, %1, %2, %3;" : "=l"(r) : "l"(a), "l"(b), "l"(c)); return r;
}
__device__ __forceinline__ ull pack2(float lo, float hi) {
    ull r;
    asm("mov.b64 %0, {%1, %2};" : "=l"(r)
        : "r"(__float_as_uint(lo)), "r"(__float_as_uint(hi)));
    return r;
}

// ---------------------------------------------------------------------------
// Single fused kernel, ONE WAVE, duty-split prologue.
//   Grid 128 = (image b, row pair y0..y0+1). Block 512 = 16 warps.
//   Phase 1 (parallel duties):
//     warps 0-7 : coefs for cp = w (both channels, 9 taps) -> packed smem
//                 tables (computed ONCE, single-rcp trick), + v1 base partial
//     warps 8-15: stage 4x34x16 tile, ch-interleaved w/ pad-18 (2-way STS max)
//   Phase 2: all 16 warps, warp = (cp = w&7, r0 = w>>3): pull 27 coef ull
//     from smem into registers, then the pipe-floor main loop (4 cg x 8 px,
//     only broadcast LDS.64 in-loop).
//   Phase 3: 8 cp-partials + base via padded smem, transposed coalesced store.
// ---------------------------------------------------------------------------
#define TCOLS 34
#define TROWS 4
#define CH_PAD 18                 // floats per (r,col) cell (9 ull): 2-way STS
#define CELL_ULL 9

#define OFF_CNP   0               // 8*9*32 ull = 18432 B per table
#define OFF_CSM   18432
#define OFF_CDSH  36864
#define OFF_TILE  55296           // 4*34*18*4 = 9792 B
#define OFF_PART  65088           // 8*64*33*4 = 67584 B
#define OFF_VPART 132672          // 8*32*4 = 1024 B
#define SMEM_BYTES 133696

__global__ __launch_bounds__(512, 1)
void apc_fused(const float* __restrict__ x,
               const float* __restrict__ pos,
               const float* __restrict__ val,
               float* __restrict__ out) {
    extern __shared__ char sm_raw[];
    ull*   c_np    = (ull*)(sm_raw + OFF_CNP);
    ull*   c_sm    = (ull*)(sm_raw + OFF_CSM);
    ull*   c_dsh   = (ull*)(sm_raw + OFF_CDSH);
    float* sm_tile = (float*)(sm_raw + OFF_TILE);
    ull*   tile64  = (ull*)sm_tile;
    float* sm_part = (float*)(sm_raw + OFF_PART);
    float* sm_vp   = (float*)(sm_raw + OFF_VPART);

    const int tid = threadIdx.x;
    const int b  = blockIdx.x >> 4;           // image
    const int y0 = (blockIdx.x & 15) << 1;    // first output row of pair
    const int w  = tid >> 5;
    const int o  = tid & 31;                  // lane = output channel

    // ==== Phase 1: duty-split prologue ====
    if (w < 8) {
        // --- coef duty: warp w = channel pair cp, computed ONCE ---
        const int cp = w;
        float vs = 0.f;
        #pragma unroll
        for (int t = 0; t < NTAP; t++) {
            float npf[2], smf[2], dsf[2];
            #pragma unroll
            for (int hf = 0; hf < 2; hf++) {
                int i = (2 * cp + hf) * NTAP + t;
                int base = (i * 32 + o) * 3;
                float p0 = pos[base], p1 = pos[base + 1], p2 = pos[base + 2];
                float v0 = val[base], v1 = val[base + 1], v2 = val[base + 2];
                float A = p1 - p0, B = p2 - p1;
                float r = __fdividef(1.f, A * B);     // 1 MUFU per triple
                float s0 = (v1 - v0) * r * B;
                float s1 = (v2 - v1) * r * A;
                npf[hf] = -p1;
                smf[hf] = 0.5f * (s0 + s1);
                dsf[hf] = 0.5f * (s1 - s0);
                vs += v1;
            }
            int ci = (cp * NTAP + t) * 32 + o;
            c_np [ci] = pack2(npf[0], npf[1]);
            c_sm [ci] = pack2(smf[0], smf[1]);
            c_dsh[ci] = pack2(dsf[0], dsf[1]);
        }
        sm_vp[cp * 32 + o] = vs;
    } else {
        // --- tile duty: rows y0-1..y0+2, cols -1..32, zero halo ---
        const float* xb = x + b * (IN_CH * H * W);
        const int tid2 = tid - 256;
        #pragma unroll
        for (int k = 0; k < 9; k++) {
            int idx = tid2 + k * 256;
            if (idx < TROWS * TCOLS * IN_CH) {
                int c   = idx / (TROWS * TCOLS);   // ch outer: coalesced LDG
                int rem = idx - c * (TROWS * TCOLS);
                int r   = rem / TCOLS;
                int col = rem - r * TCOLS;
                int gy = y0 + r - 1;
                int gx = col - 1;
                float v = 0.f;
                if ((unsigned)gy < (unsigned)H && (unsigned)gx < (unsigned)W)
                    v = xb[(c * H + gy) * W + gx];
                sm_tile[(r * TCOLS + col) * CH_PAD + c] = v;
            }
        }
    }
    __syncthreads();

    // ==== Phase 2: main. warp = (cp, r0); coefs smem -> registers ====
    const int cp = w & 7;
    const int r0 = w >> 3;
    ull cnp[NTAP], csm[NTAP], cdsh[NTAP];
    {
        const ull* pn = c_np  + (cp * NTAP) * 32 + o;
        const ull* ps = c_sm  + (cp * NTAP) * 32 + o;
        const ull* pd = c_dsh + (cp * NTAP) * 32 + o;
        #pragma unroll
        for (int t = 0; t < NTAP; t++) {
            cnp[t]  = pn[t * 32];
            csm[t]  = ps[t * 32];
            cdsh[t] = pd[t * 32];
        }
    }

    const ull ABS2 = 0x7FFFFFFF7FFFFFFFull;
    #pragma unroll
    for (int cg = 0; cg < 4; cg++) {
        const int c0 = cg << 3;
        ull acc[8] = {0, 0, 0, 0, 0, 0, 0, 0};

        #pragma unroll
        for (int kh = 0; kh < 3; kh++) {
            // window row r0+kh: 10 pair-values, warp-uniform broadcast LDS.64
            ull xr[10];
            #pragma unroll
            for (int m = 0; m < 10; m++)
                xr[m] = tile64[((r0 + kh) * TCOLS + c0 + m) * CELL_ULL + cp];

            #pragma unroll
            for (int kw = 0; kw < 3; kw++) {
                const int t = kh * 3 + kw;
                const ull np1 = cnp[t];
                const ull smv = csm[t];
                const ull dsh = cdsh[t];
                #pragma unroll
                for (int p = 0; p < 8; p++) {
                    ull d = add2(xr[p + kw], np1);
                    ull a = d & ABS2;
                    acc[p] = fma2(smv, d, acc[p]);
                    acc[p] = fma2(dsh, a, acc[p]);
                }
            }
        }

        // horizontal pair reduce -> padded smem partials (lanes contiguous)
        #pragma unroll
        for (int p = 0; p < 8; p++) {
            float lo = __uint_as_float((unsigned)acc[p]);
            float hi = __uint_as_float((unsigned)(acc[p] >> 32));
            sm_part[(cp * 64 + (r0 << 5) + c0 + p) * 33 + o] = lo + hi;
        }
    }
    __syncthreads();

    // ==== Phase 3: combine 8 cp-partials + base; transposed store ====
    #pragma unroll
    for (int k = 0; k < 4; k++) {
        int q  = tid + k * 512;       // (oo = q>>6 warp-uniform, px = q&63)
        int oo = q >> 6;
        int px = q & 63;
        float s = 0.f;
        #pragma unroll
        for (int g = 0; g < NCP; g++)
            s += sm_vp[g * 32 + oo];                // warp-uniform broadcast
        #pragma unroll
        for (int g = 0; g < NCP; g++)
            s += sm_part[(g * 64 + px) * 33 + oo];  // stride-33: conflict-free
        int r = px >> 5, col = px & 31;
        out[((b * OUT_CH + oo) * H + (y0 + r)) * W + col] = s;
    }
}

extern "C" void kernel_launch(void* const* d_in, const int* in_sizes, int n_in,
                              void* d_out, int out_size) {
    const float* x   = (const float*)d_in[0];
    const float* pos = (const float*)d_in[1];
    const float* val = (const float*)d_in[2];
    float* out = (float*)d_out;

    cudaFuncSetAttribute(apc_fused, cudaFuncAttributeMaxDynamicSharedMemorySize,
                         SMEM_BYTES);
    apc_fused<<<BATCH * (H / 2), 512, SMEM_BYTES>>>(x, pos, val, out);
}

// round 12
// speedup vs baseline: 1.1348x; 1.1348x over previous
#include <cuda_runtime.h>
#include <cstdint>

#define IN_CH 16
#define OUT_CH 32
#define BATCH 8
#define H 32
#define W 32
#define NCP (IN_CH / 2)            // 8 channel pairs
#define NTAP 9

typedef unsigned long long ull;

__device__ __forceinline__ ull add2(ull a, ull b) {
    ull r; asm("add.rn.f32x2 %0, %1, %2;" : "=l"(r) : "l"(a), "l"(b)); return r;
}
__device__ __forceinline__ ull fma2(ull a, ull b, ull c) {
    ull r; asm("fma.rn.f32x2 %0, %1, %2, %3;" : "=l"(r) : "l"(a), "l"(b), "l"(c)); return r;
}
__device__ __forceinline__ ull pack2(float lo, float hi) {
    ull r;
    asm("mov.b64 %0, {%1, %2};" : "=l"(r)
        : "r"(__float_as_uint(lo)), "r"(__float_as_uint(hi)));
    return r;
}

// ---------------------------------------------------------------------------
// Single fused kernel, ONE WAVE, flat prologue.
//   Grid 128 = (image b, row pair y0..y0+1). Block 512 = 16 warps.
//   Warp w = (cp = w&7, half = w>>3). lane = output channel o.
//   Prologue (every warp, one MLP hump):
//     1. prefetch tile slice into regs (5 guarded LDG)
//     2. coef LDGs + compute for taps [half]: 0-4 or 5-8 (single-rcp trick)
//     3. STS tile, STS coef tables, STS v1-partials
//   Main: warp = (cp, r0=half): coefs smem->regs (27 LDS.64), base term
//     folded into acc init; 4 col-groups x 8 px, only broadcast LDS in-loop.
//   Epilogue: sum 8 cp-partials (no vpart pass), transposed coalesced store.
// ---------------------------------------------------------------------------
#define TCOLS 34
#define TROWS 4
#define NCELL (TROWS * TCOLS)         // 136 cells
#define CELLF 18                      // floats per cell (pad: 2-way STS max)
#define CELL_ULL 9
#define TILE_FLOATS (NCELL * IN_CH)   // 2176 logical elements

#define OFF_CNP   0                   // 8*9*32 ull = 18432 B per table
#define OFF_CSM   18432
#define OFF_CDSH  36864
#define OFF_TILE  55296               // 136*18*4 = 9792 B
#define OFF_PART  65088               // 8*64*33*4 = 67584 B
#define OFF_VSUM  132672              // 8*2*32*4 = 2048 B
#define SMEM_BYTES 134720

__global__ __launch_bounds__(512, 1)
void apc_fused(const float* __restrict__ x,
               const float* __restrict__ pos,
               const float* __restrict__ val,
               float* __restrict__ out) {
    extern __shared__ char sm_raw[];
    ull*   c_np    = (ull*)(sm_raw + OFF_CNP);
    ull*   c_sm    = (ull*)(sm_raw + OFF_CSM);
    ull*   c_dsh   = (ull*)(sm_raw + OFF_CDSH);
    float* sm_tile = (float*)(sm_raw + OFF_TILE);
    ull*   tile64  = (ull*)sm_tile;
    float* sm_part = (float*)(sm_raw + OFF_PART);
    float* sm_vs   = (float*)(sm_raw + OFF_VSUM);

    const int tid = threadIdx.x;
    const int b  = blockIdx.x >> 4;           // image
    const int y0 = (blockIdx.x & 15) << 1;    // first output row of pair
    const int w  = tid >> 5;
    const int o  = tid & 31;                  // lane = output channel
    const int cp   = w & 7;                   // channel pair
    const int half = w >> 3;                  // tap half / row of pair

    // ==== Prologue step 1: prefetch tile slice into registers ====
    const float* xb = x + b * (IN_CH * H * W);
    float tv[5];
    #pragma unroll
    for (int k = 0; k < 5; k++) {
        int idx = tid + k * 512;
        float v = 0.f;
        if (idx < TILE_FLOATS) {
            int c   = idx / NCELL;            // channel outer: coalesced LDG
            int rem = idx - c * NCELL;
            int r   = rem / TCOLS;
            int col = rem - r * TCOLS;
            int gy = y0 + r - 1;
            int gx = col - 1;
            if ((unsigned)gy < (unsigned)H && (unsigned)gx < (unsigned)W)
                v = xb[(c * H + gy) * W + gx];
        }
        tv[k] = v;
    }

    // ==== Prologue step 2: coefs for taps [t0, t0+tn), both channels ====
    //   y_i(x) = v1 + sm*d + dsh*|d|, d = x - p1
    {
        const int t0 = half ? 5 : 0;
        const int tn = half ? 4 : 5;
        float vs = 0.f;
        #pragma unroll
        for (int tt = 0; tt < 5; tt++) {
            if (tt < tn) {
                const int t = t0 + tt;
                float npf[2], smf[2], dsf[2];
                #pragma unroll
                for (int hf = 0; hf < 2; hf++) {
                    int i = (2 * cp + hf) * NTAP + t;
                    int base = (i * 32 + o) * 3;
                    float p0 = pos[base], p1 = pos[base + 1], p2 = pos[base + 2];
                    float v0 = val[base], v1 = val[base + 1], v2 = val[base + 2];
                    float A = p1 - p0, B = p2 - p1;
                    float r = __fdividef(1.f, A * B);   // 1 MUFU per triple
                    float s0 = (v1 - v0) * r * B;
                    float s1 = (v2 - v1) * r * A;
                    npf[hf] = -p1;
                    smf[hf] = 0.5f * (s0 + s1);
                    dsf[hf] = 0.5f * (s1 - s0);
                    vs += v1;
                }
                int ci = (cp * NTAP + t) * 32 + o;
                c_np [ci] = pack2(npf[0], npf[1]);
                c_sm [ci] = pack2(smf[0], smf[1]);
                c_dsh[ci] = pack2(dsf[0], dsf[1]);
            }
        }
        sm_vs[(cp * 2 + half) * 32 + o] = vs;
    }

    // ==== Prologue step 3: store tile slice (pad-18 cells, 2-way STS) ====
    #pragma unroll
    for (int k = 0; k < 5; k++) {
        int idx = tid + k * 512;
        if (idx < TILE_FLOATS) {
            int c   = idx / NCELL;
            int rem = idx - c * NCELL;
            sm_tile[rem * CELLF + c] = tv[k];
        }
    }
    __syncthreads();

    // ==== Main: warp = (cp, r0 = half). Coefs smem -> registers ====
    const int r0 = half;
    ull cnp[NTAP], csm[NTAP], cdsh[NTAP];
    {
        const ull* pn = c_np  + (cp * NTAP) * 32 + o;
        const ull* ps = c_sm  + (cp * NTAP) * 32 + o;
        const ull* pd = c_dsh + (cp * NTAP) * 32 + o;
        #pragma unroll
        for (int t = 0; t < NTAP; t++) {
            cnp[t]  = pn[t * 32];
            csm[t]  = ps[t * 32];
            cdsh[t] = pd[t * 32];
        }
    }
    // base term for this cp (both halves), folded into acc initialization
    const float vsall = sm_vs[(cp * 2) * 32 + o] + sm_vs[(cp * 2 + 1) * 32 + o];
    const ull accInit = pack2(vsall, 0.f);

    const ull ABS2 = 0x7FFFFFFF7FFFFFFFull;
    #pragma unroll
    for (int cg = 0; cg < 4; cg++) {
        const int c0 = cg << 3;
        ull acc[8];
        #pragma unroll
        for (int p = 0; p < 8; p++) acc[p] = accInit;

        #pragma unroll
        for (int kh = 0; kh < 3; kh++) {
            // window row r0+kh: 10 pair-values, warp-uniform broadcast LDS.64
            ull xr[10];
            #pragma unroll
            for (int m = 0; m < 10; m++)
                xr[m] = tile64[((r0 + kh) * TCOLS + c0 + m) * CELL_ULL + cp];

            #pragma unroll
            for (int kw = 0; kw < 3; kw++) {
                const int t = kh * 3 + kw;
                const ull np1 = cnp[t];
                const ull smv = csm[t];
                const ull dsh = cdsh[t];
                #pragma unroll
                for (int p = 0; p < 8; p++) {
                    ull d = add2(xr[p + kw], np1);
                    ull a = d & ABS2;
                    acc[p] = fma2(smv, d, acc[p]);
                    acc[p] = fma2(dsh, a, acc[p]);
                }
            }
        }

        // horizontal pair reduce -> padded smem partials (lanes contiguous)
        #pragma unroll
        for (int p = 0; p < 8; p++) {
            float lo = __uint_as_float((unsigned)acc[p]);
            float hi = __uint_as_float((unsigned)(acc[p] >> 32));
            sm_part[(cp * 64 + (r0 << 5) + c0 + p) * 33 + o] = lo + hi;
        }
    }
    __syncthreads();

    // ==== Epilogue: sum 8 cp-partials; transposed coalesced store ====
    #pragma unroll
    for (int k = 0; k < 4; k++) {
        int q  = tid + k * 512;       // (oo = q>>6 warp-uniform, px = q&63)
        int oo = q >> 6;
        int px = q & 63;
        float s = 0.f;
        #pragma unroll
        for (int g = 0; g < NCP; g++)
            s += sm_part[(g * 64 + px) * 33 + oo];  // stride-33: conflict-free
        int r = px >> 5, col = px & 31;
        out[((b * OUT_CH + oo) * H + (y0 + r)) * W + col] = s;
    }
}

extern "C" void kernel_launch(void* const* d_in, const int* in_sizes, int n_in,
                              void* d_out, int out_size) {
    const float* x   = (const float*)d_in[0];
    const float* pos = (const float*)d_in[1];
    const float* val = (const float*)d_in[2];
    float* out = (float*)d_out;

    cudaFuncSetAttribute(apc_fused, cudaFuncAttributeMaxDynamicSharedMemorySize,
                         SMEM_BYTES);
    apc_fused<<<BATCH * (H / 2), 512, SMEM_BYTES>>>(x, pos, val, out);
}